// round 8
// baseline (speedup 1.0000x reference)
#include <cuda_runtime.h>

#define NN 100000
#define NE 1600000
#define EMB 128
#define CDIM 32
#define NNP 100096          // 391 * 256
#define NBLK_SCAN 391
#define MT 256              // gemm row tile
#define BN_EPS 1e-5f

typedef unsigned long long ull;

// ---------------- device scratch (static, no allocations) ----------------
__device__ __align__(16) float g_p[NN * EMB];   // p = h @ W1
__device__ __align__(16) float g_q[NN * EMB];   // q = (1+eps)p + b1 + agg
__device__ int   g_srcs[NE];
__device__ int   g_cnt[NNP];
__device__ int   g_offA[NNP];
__device__ int   g_off[NN + 1];
__device__ int   g_cur[NN];
__device__ int   g_bsum[NBLK_SCAN];
__device__ int   g_bsumx[NBLK_SCAN];
__device__ float g_u[EMB], g_v[EMB];
__device__ float g_sum[EMB], g_sumsq[EMB];
__device__ int   g_ei_is64;

// ---------------- f32x2 packed helpers -----------------------------------
__device__ __forceinline__ ull pk2(float a, float b) {
    ull r;
    asm("mov.b64 %0, {%1,%2};" : "=l"(r) : "f"(a), "f"(b));
    return r;
}
__device__ __forceinline__ void upk2(ull v, float& a, float& b) {
    asm("mov.b64 {%0,%1}, %2;" : "=f"(a), "=f"(b) : "l"(v));
}
__device__ __forceinline__ void fma2(ull& d, ull a, ull b) {
    asm("fma.rn.f32x2 %0, %1, %2, %0;" : "+l"(d) : "l"(a), "l"(b));
}

// ---------------- init: zero counts + dtype detect + u,v prep -------------
__global__ void __launch_bounds__(256) init_kernel(
    const int* __restrict__ ei32, const float* __restrict__ cW,
    const float* __restrict__ cb, const float* __restrict__ W1) {
    int i = blockIdx.x * 256 + threadIdx.x;
    if (i < NNP) g_cnt[i] = 0;
    if (blockIdx.x == 0) {
        int t = threadIdx.x;
        if (t < EMB) {
            float u = 0.f, v = 0.f;
#pragma unroll
            for (int k = 0; k < CDIM; k++) {
                float w = W1[(EMB + k) * EMB + t];
                u = fmaf(cW[k], w, u);
                v = fmaf(cb[k], w, v);
            }
            g_u[t] = u; g_v[t] = v;
            g_sum[t] = 0.f; g_sumsq[t] = 0.f;
        }
        if (t == 0) {
            int all_zero = 1;
            for (int j = 1; j < 64; j += 2)
                if (ei32[j] != 0) all_zero = 0;
            g_ei_is64 = all_zero;
        }
    }
}

// ---------------- CSR build ------------------------------------------------
__global__ void __launch_bounds__(256) hist_kernel(const void* __restrict__ ei_raw) {
    int is64 = g_ei_is64;
    int e0 = (blockIdx.x * 256 + threadIdx.x) * 4;
    if (e0 >= NE) return;
    int d[4];
    if (is64) {
        const longlong2* p = (const longlong2*)ei_raw;
        longlong2 a = __ldg(p + (NE + e0) / 2);
        longlong2 b = __ldg(p + (NE + e0) / 2 + 1);
        d[0] = (int)a.x; d[1] = (int)a.y; d[2] = (int)b.x; d[3] = (int)b.y;
    } else {
        const int4* p = (const int4*)ei_raw;
        int4 a = __ldg(p + (NE + e0) / 4);
        d[0] = a.x; d[1] = a.y; d[2] = a.z; d[3] = a.w;
    }
#pragma unroll
    for (int j = 0; j < 4; j++) atomicAdd(&g_cnt[d[j]], 1);
}

template <int NW>
__device__ __forceinline__ int block_scan_incl(int v, int* ws) {
    int lane = threadIdx.x & 31, w = threadIdx.x >> 5;
#pragma unroll
    for (int d = 1; d < 32; d <<= 1) {
        int n = __shfl_up_sync(0xffffffffu, v, d);
        if (lane >= d) v += n;
    }
    if (lane == 31) ws[w] = v;
    __syncthreads();
    if (w == 0) {
        int s = (lane < NW) ? ws[lane] : 0;
#pragma unroll
        for (int d = 1; d < 32; d <<= 1) {
            int n = __shfl_up_sync(0xffffffffu, s, d);
            if (lane >= d) s += n;
        }
        if (lane < NW) ws[lane] = s;
    }
    __syncthreads();
    if (w > 0) v += ws[w - 1];
    return v;
}

__global__ void __launch_bounds__(256) scan1_kernel() {
    __shared__ int ws[8];
    int idx = blockIdx.x * 256 + threadIdx.x;
    int v = g_cnt[idx];
    int incl = block_scan_incl<8>(v, ws);
    g_offA[idx] = incl - v;
    if (threadIdx.x == 255) g_bsum[blockIdx.x] = incl;
}

__global__ void __launch_bounds__(512) scan2_kernel() {
    __shared__ int ws[16];
    int t = threadIdx.x;
    int v = (t < NBLK_SCAN) ? g_bsum[t] : 0;
    int incl = block_scan_incl<16>(v, ws);
    if (t < NBLK_SCAN) g_bsumx[t] = incl - v;
}

__global__ void __launch_bounds__(256) scan3_kernel() {
    int idx = blockIdx.x * 256 + threadIdx.x;
    if (idx < NN) {
        int o = g_offA[idx] + g_bsumx[idx >> 8];
        g_off[idx] = o;
        g_cur[idx] = o;
    }
    if (idx == 0) g_off[NN] = NE;
}

__global__ void __launch_bounds__(256) fill_kernel(const void* __restrict__ ei_raw) {
    int is64 = g_ei_is64;
    int e0 = (blockIdx.x * 256 + threadIdx.x) * 4;
    if (e0 >= NE) return;
    int s[4], d[4];
    if (is64) {
        const longlong2* p = (const longlong2*)ei_raw;
        longlong2 a = __ldg(p + e0 / 2);
        longlong2 b = __ldg(p + e0 / 2 + 1);
        longlong2 c2 = __ldg(p + (NE + e0) / 2);
        longlong2 d2 = __ldg(p + (NE + e0) / 2 + 1);
        s[0] = (int)a.x; s[1] = (int)a.y; s[2] = (int)b.x; s[3] = (int)b.y;
        d[0] = (int)c2.x; d[1] = (int)c2.y; d[2] = (int)d2.x; d[3] = (int)d2.y;
    } else {
        const int4* p = (const int4*)ei_raw;
        int4 a = __ldg(p + e0 / 4);
        int4 b = __ldg(p + (NE + e0) / 4);
        s[0] = a.x; s[1] = a.y; s[2] = a.z; s[3] = a.w;
        d[0] = b.x; d[1] = b.y; d[2] = b.z; d[3] = b.w;
    }
#pragma unroll
    for (int j = 0; j < 4; j++) {
        int pos = atomicAdd(&g_cur[d[j]], 1);
        g_srcs[pos] = s[j];
    }
}

// ---------------- GEMM A: p = x@W1a + c*u + v ------------------------------
// 256-row x 128-col tile, 512 threads, 8x8 per thread via f32x2.
__global__ void __launch_bounds__(512) gemmA_kernel(
    const float* __restrict__ x, const float* __restrict__ c,
    const float* __restrict__ W1) {
    extern __shared__ float sm[];
    float* Ws = sm;               // [128][128]
    float* Xs = sm + EMB * EMB;   // [256][128] row-major

    int tid = threadIdx.x;
    int row0 = blockIdx.x * MT;

    float4* Ws4 = (float4*)Ws;
    const float4* W14 = (const float4*)W1;
    for (int i = tid; i < EMB * EMB / 4; i += 512) Ws4[i] = W14[i];

    float4* Xs4 = (float4*)Xs;
    const float4* X4 = (const float4*)x;
    for (int i = tid; i < MT * 32; i += 512) {
        int r = i >> 5, ch = i & 31;
        int row = row0 + r;
        Xs4[i] = (row < NN) ? X4[row * 32 + ch] : make_float4(0.f, 0.f, 0.f, 0.f);
    }
    __syncthreads();

    int cg = tid & 15;    // cols cg*8 .. cg*8+7
    int rg = tid >> 4;    // rows rg*8 .. rg*8+7 (0..31)
    ull acc[8][4];
#pragma unroll
    for (int j = 0; j < 8; j++)
#pragma unroll
        for (int q = 0; q < 4; q++) acc[j][q] = 0ull;

    const float* zb = Xs + rg * 8 * EMB;
#pragma unroll 4
    for (int k = 0; k < EMB; k++) {
        const ull* wp = (const ull*)(Ws + k * EMB + cg * 8);
        ull w01 = wp[0], w23 = wp[1], w45 = wp[2], w67 = wp[3];
#pragma unroll
        for (int j = 0; j < 8; j++) {
            float z = zb[j * EMB + k];
            ull zz = pk2(z, z);
            fma2(acc[j][0], zz, w01);
            fma2(acc[j][1], zz, w23);
            fma2(acc[j][2], zz, w45);
            fma2(acc[j][3], zz, w67);
        }
    }

    float4 uA = ((const float4*)g_u)[cg * 2], uB = ((const float4*)g_u)[cg * 2 + 1];
    float4 vA = ((const float4*)g_v)[cg * 2], vB = ((const float4*)g_v)[cg * 2 + 1];

#pragma unroll
    for (int j = 0; j < 8; j++) {
        int row = row0 + rg * 8 + j;
        if (row < NN) {
            float o[8];
            upk2(acc[j][0], o[0], o[1]);
            upk2(acc[j][1], o[2], o[3]);
            upk2(acc[j][2], o[4], o[5]);
            upk2(acc[j][3], o[6], o[7]);
            float cv = __ldg(c + row);
            float4 pA, pB;
            pA.x = fmaf(cv, uA.x, o[0] + vA.x);
            pA.y = fmaf(cv, uA.y, o[1] + vA.y);
            pA.z = fmaf(cv, uA.z, o[2] + vA.z);
            pA.w = fmaf(cv, uA.w, o[3] + vA.w);
            pB.x = fmaf(cv, uB.x, o[4] + vB.x);
            pB.y = fmaf(cv, uB.y, o[5] + vB.y);
            pB.z = fmaf(cv, uB.z, o[6] + vB.z);
            pB.w = fmaf(cv, uB.w, o[7] + vB.w);
            ((float4*)g_p)[row * 32 + cg * 2]     = pA;
            ((float4*)g_p)[row * 32 + cg * 2 + 1] = pB;
        }
    }
}

// ---------------- gather: q[n] = (1+eps)p[n]+b1 + sum p[srcs], + BN stats --
__global__ void __launch_bounds__(256) gather_kernel(
    const float* __restrict__ eps, const float* __restrict__ b1) {
    __shared__ float s_sum[EMB], s_sq[EMB];
    int tid = threadIdx.x;
    if (tid < EMB) { s_sum[tid] = 0.f; s_sq[tid] = 0.f; }
    __syncthreads();

    int lane = tid & 31;
    int gw = blockIdx.x * 8 + (tid >> 5);
    int nw = gridDim.x * 8;
    const float4* P4 = (const float4*)g_p;
    float4* Q4 = (float4*)g_q;

    float ep = 1.0f + __ldg(eps);
    float4 b1v = __ldg(((const float4*)b1) + lane);

    float4 csum = make_float4(0.f, 0.f, 0.f, 0.f);
    float4 csq  = make_float4(0.f, 0.f, 0.f, 0.f);

    for (int n = gw; n < NN; n += nw) {
        int s0 = g_off[n], s1 = g_off[n + 1];
        float4 pn = __ldg(P4 + n * 32 + lane);
        float4 a0, a1;
        a0.x = fmaf(ep, pn.x, b1v.x);
        a0.y = fmaf(ep, pn.y, b1v.y);
        a0.z = fmaf(ep, pn.z, b1v.z);
        a0.w = fmaf(ep, pn.w, b1v.w);
        a1 = make_float4(0.f, 0.f, 0.f, 0.f);
        int e = s0;
        for (; e + 3 < s1; e += 4) {
            int i0 = g_srcs[e],     i1 = g_srcs[e + 1];
            int i2 = g_srcs[e + 2], i3 = g_srcs[e + 3];
            float4 v0 = __ldg(P4 + i0 * 32 + lane);
            float4 v1 = __ldg(P4 + i1 * 32 + lane);
            float4 v2 = __ldg(P4 + i2 * 32 + lane);
            float4 v3 = __ldg(P4 + i3 * 32 + lane);
            a0.x += v0.x + v1.x; a0.y += v0.y + v1.y;
            a0.z += v0.z + v1.z; a0.w += v0.w + v1.w;
            a1.x += v2.x + v3.x; a1.y += v2.y + v3.y;
            a1.z += v2.z + v3.z; a1.w += v2.w + v3.w;
        }
        for (; e < s1; e++) {
            float4 v = __ldg(P4 + g_srcs[e] * 32 + lane);
            a1.x += v.x; a1.y += v.y; a1.z += v.z; a1.w += v.w;
        }
        float4 acc;
        acc.x = a0.x + a1.x; acc.y = a0.y + a1.y;
        acc.z = a0.z + a1.z; acc.w = a0.w + a1.w;
        Q4[n * 32 + lane] = acc;
        csum.x += acc.x; csum.y += acc.y; csum.z += acc.z; csum.w += acc.w;
        csq.x = fmaf(acc.x, acc.x, csq.x);
        csq.y = fmaf(acc.y, acc.y, csq.y);
        csq.z = fmaf(acc.z, acc.z, csq.z);
        csq.w = fmaf(acc.w, acc.w, csq.w);
    }

    atomicAdd(&s_sum[lane * 4 + 0], csum.x);
    atomicAdd(&s_sum[lane * 4 + 1], csum.y);
    atomicAdd(&s_sum[lane * 4 + 2], csum.z);
    atomicAdd(&s_sum[lane * 4 + 3], csum.w);
    atomicAdd(&s_sq[lane * 4 + 0], csq.x);
    atomicAdd(&s_sq[lane * 4 + 1], csq.y);
    atomicAdd(&s_sq[lane * 4 + 2], csq.z);
    atomicAdd(&s_sq[lane * 4 + 3], csq.w);
    __syncthreads();
    if (tid < EMB) {
        atomicAdd(&g_sum[tid],   s_sum[tid]);
        atomicAdd(&g_sumsq[tid], s_sq[tid]);
    }
}

// ---------------- GEMM 2: out = relu(bn(q)) @ W2 + b2 (BN fused) ---------
__global__ void __launch_bounds__(512) gemm2_kernel(
    const float* __restrict__ W2, const float* __restrict__ b2,
    const float* __restrict__ gamma, const float* __restrict__ beta,
    float* __restrict__ out) {
    extern __shared__ float sm[];
    float* Ws  = sm;                        // [128][128]
    float* Ys  = sm + EMB * EMB;            // [256][128]
    float* scs = Ys + MT * EMB;             // [128]
    float* shs = scs + EMB;                 // [128]

    int tid = threadIdx.x;
    int row0 = blockIdx.x * MT;

    // fused BN finalize: per-block recompute of scale/shift
    if (tid < EMB) {
        const float invN = 1.0f / (float)NN;
        float mu  = g_sum[tid] * invN;
        float var = g_sumsq[tid] * invN - mu * mu;
        float sc  = __ldg(gamma + tid) * rsqrtf(var + BN_EPS);
        scs[tid] = sc;
        shs[tid] = __ldg(beta + tid) - mu * sc;
    }

    float4* Ws4 = (float4*)Ws;
    const float4* W24 = (const float4*)W2;
    for (int i = tid; i < EMB * EMB / 4; i += 512) Ws4[i] = W24[i];
    __syncthreads();

    float4* Ys4 = (float4*)Ys;
    const float4* Q4 = (const float4*)g_q;
    for (int i = tid; i < MT * 32; i += 512) {
        int r = i >> 5, ch = i & 31;
        int row = row0 + r;
        float4 v = (row < NN) ? Q4[row * 32 + ch] : make_float4(0.f, 0.f, 0.f, 0.f);
        int k0 = ch * 4;
        v.x = fmaxf(fmaf(v.x, scs[k0 + 0], shs[k0 + 0]), 0.f);
        v.y = fmaxf(fmaf(v.y, scs[k0 + 1], shs[k0 + 1]), 0.f);
        v.z = fmaxf(fmaf(v.z, scs[k0 + 2], shs[k0 + 2]), 0.f);
        v.w = fmaxf(fmaf(v.w, scs[k0 + 3], shs[k0 + 3]), 0.f);
        Ys4[i] = v;
    }
    __syncthreads();

    int cg = tid & 15;
    int rg = tid >> 4;
    ull acc[8][4];
#pragma unroll
    for (int j = 0; j < 8; j++)
#pragma unroll
        for (int q = 0; q < 4; q++) acc[j][q] = 0ull;

    const float* zb = Ys + rg * 8 * EMB;
#pragma unroll 4
    for (int k = 0; k < EMB; k++) {
        const ull* wp = (const ull*)(Ws + k * EMB + cg * 8);
        ull w01 = wp[0], w23 = wp[1], w45 = wp[2], w67 = wp[3];
#pragma unroll
        for (int j = 0; j < 8; j++) {
            float z = zb[j * EMB + k];
            ull zz = pk2(z, z);
            fma2(acc[j][0], zz, w01);
            fma2(acc[j][1], zz, w23);
            fma2(acc[j][2], zz, w45);
            fma2(acc[j][3], zz, w67);
        }
    }

    float4 bA = ((const float4*)b2)[cg * 2], bB = ((const float4*)b2)[cg * 2 + 1];
#pragma unroll
    for (int j = 0; j < 8; j++) {
        int row = row0 + rg * 8 + j;
        if (row < NN) {
            float o[8];
            upk2(acc[j][0], o[0], o[1]);
            upk2(acc[j][1], o[2], o[3]);
            upk2(acc[j][2], o[4], o[5]);
            upk2(acc[j][3], o[6], o[7]);
            float4 oA, oB;
            oA.x = o[0] + bA.x; oA.y = o[1] + bA.y;
            oA.z = o[2] + bA.z; oA.w = o[3] + bA.w;
            oB.x = o[4] + bB.x; oB.y = o[5] + bB.y;
            oB.z = o[6] + bB.z; oB.w = o[7] + bB.w;
            ((float4*)out)[row * 32 + cg * 2]     = oA;
            ((float4*)out)[row * 32 + cg * 2 + 1] = oB;
        }
    }
}

// ---------------- launch ---------------------------------------------------
extern "C" void kernel_launch(void* const* d_in, const int* in_sizes, int n_in,
                              void* d_out, int out_size) {
    const float* x     = (const float*)d_in[0];
    const float* c     = (const float*)d_in[1];
    const void*  ei    = d_in[2];
    const float* cW    = (const float*)d_in[3];
    const float* cb    = (const float*)d_in[4];
    const float* eps   = (const float*)d_in[5];
    const float* W1    = (const float*)d_in[6];
    const float* b1    = (const float*)d_in[7];
    const float* gamma = (const float*)d_in[8];
    const float* beta  = (const float*)d_in[9];
    const float* W2    = (const float*)d_in[10];
    const float* b2    = (const float*)d_in[11];
    float* out = (float*)d_out;

    static cudaStream_t s2 = nullptr;
    static cudaEvent_t evFork = nullptr, evJoin = nullptr;
    if (s2 == nullptr) {
        cudaStreamCreateWithFlags(&s2, cudaStreamNonBlocking);
        cudaEventCreateWithFlags(&evFork, cudaEventDisableTiming);
        cudaEventCreateWithFlags(&evJoin, cudaEventDisableTiming);
    }

    const int SMEM_A = (EMB * EMB + MT * EMB) * 4;            // 196608
    const int SMEM_2 = (EMB * EMB + MT * EMB + 2 * EMB) * 4;  // 197632
    cudaFuncSetAttribute(gemmA_kernel, cudaFuncAttributeMaxDynamicSharedMemorySize, SMEM_A);
    cudaFuncSetAttribute(gemm2_kernel, cudaFuncAttributeMaxDynamicSharedMemorySize, SMEM_2);

    int gemm_blocks = (NN + MT - 1) / MT;   // 391
    int ecsr_blocks = (NE / 4 + 255) / 256; // 1563

    init_kernel<<<NNP / 256, 256>>>((const int*)ei, cW, cb, W1);

    // fork: CSR build on side stream
    cudaEventRecord(evFork, 0);
    cudaStreamWaitEvent(s2, evFork, 0);
    hist_kernel<<<ecsr_blocks, 256, 0, s2>>>(ei);
    scan1_kernel<<<NBLK_SCAN, 256, 0, s2>>>();
    scan2_kernel<<<1, 512, 0, s2>>>();
    scan3_kernel<<<NBLK_SCAN, 256, 0, s2>>>();
    fill_kernel<<<ecsr_blocks, 256, 0, s2>>>(ei);
    cudaEventRecord(evJoin, s2);

    // main: GEMM A
    gemmA_kernel<<<gemm_blocks, 512, SMEM_A>>>(x, c, W1);

    cudaStreamWaitEvent(0, evJoin, 0);

    gather_kernel<<<1184, 256>>>(eps, b1);
    gemm2_kernel<<<gemm_blocks, 512, SMEM_2>>>(W2, b2, gamma, beta, out);
}